// round 9
// baseline (speedup 1.0000x reference)
#include <cuda_runtime.h>
#include <cuda_bf16.h>
#include <cstdint>
#include <math.h>

// Problem constants
#define BATCH 2
#define SEQ   2048
#define DMODEL 1024
#define NHEAD 16
#define HD    64
#define M_ROWS (BATCH*SEQ)        // 4096
#define QKV_N  (3*DMODEL)         // 3072

// Scratch (device globals; allocation is forbidden)
__device__ float g_qkv[(size_t)M_ROWS * QKV_N];    // 48 MB
__device__ float g_att[(size_t)M_ROWS * DMODEL];   // 16 MB
// bf16 hi/lo packed operands
__device__ __nv_bfloat16 g_wTh[(size_t)(QKV_N + DMODEL) * DMODEL];  // 8 MB
__device__ __nv_bfloat16 g_wTl[(size_t)(QKV_N + DMODEL) * DMODEL];  // 8 MB
__device__ __nv_bfloat16 g_xh[(size_t)M_ROWS * DMODEL];             // 8 MB
__device__ __nv_bfloat16 g_xl[(size_t)M_ROWS * DMODEL];             // 8 MB

// ===========================================================================
// PTX helpers
// ===========================================================================
__device__ __forceinline__ uint32_t smem_u32(const void* p) {
    uint32_t a;
    asm("{ .reg .u64 t; cvta.to.shared.u64 t, %1; cvt.u32.u64 %0, t; }"
        : "=r"(a) : "l"(p));
    return a;
}
__device__ __forceinline__ void cp_async16(uint32_t s, const void* g) {
    asm volatile("cp.async.cg.shared.global [%0], [%1], 16;" :: "r"(s), "l"(g));
}
__device__ __forceinline__ void cp_commit() {
    asm volatile("cp.async.commit_group;" ::: "memory");
}
template<int N> __device__ __forceinline__ void cp_wait() {
    asm volatile("cp.async.wait_group %0;" :: "n"(N) : "memory");
}

// bf16 mma: D[16x8] += A[16x16] * B[16x8]  (row.col)
__device__ __forceinline__ void mma_bf16(float* c, const uint32_t* a, const uint32_t* b) {
    asm volatile(
        "mma.sync.aligned.m16n8k16.row.col.f32.bf16.bf16.f32 "
        "{%0,%1,%2,%3}, {%4,%5,%6,%7}, {%8,%9}, {%0,%1,%2,%3};"
        : "+f"(c[0]), "+f"(c[1]), "+f"(c[2]), "+f"(c[3])
        : "r"(a[0]), "r"(a[1]), "r"(a[2]), "r"(a[3]), "r"(b[0]), "r"(b[1]));
}

// Split 2 fp32 -> packed bf16 hi word + packed bf16 lo (residual) word
__device__ __forceinline__ void bf16_split2(float x, float y, uint32_t& h, uint32_t& l) {
    asm("cvt.rn.bf16x2.f32 %0, %1, %2;" : "=r"(h) : "f"(y), "f"(x));
    float rx = x - __uint_as_float(h << 16);
    float ry = y - __uint_as_float(h & 0xFFFF0000u);
    asm("cvt.rn.bf16x2.f32 %0, %1, %2;" : "=r"(l) : "f"(ry), "f"(rx));
}

// ===========================================================================
// Pre-pass: elementwise split fp32 -> packed bf16 hi/lo
// ===========================================================================
__global__ void split_pack(const float* __restrict__ in,
                           __nv_bfloat16* __restrict__ hi,
                           __nv_bfloat16* __restrict__ lo, int n4)
{
    int i = blockIdx.x * blockDim.x + threadIdx.x;
    if (i >= n4) return;
    float4 v = *(const float4*)(in + (size_t)i * 4);
    uint32_t h0, h1, l0, l1;
    bf16_split2(v.x, v.y, h0, l0);
    bf16_split2(v.z, v.w, h1, l1);
    ((uint2*)hi)[i] = make_uint2(h0, h1);
    ((uint2*)lo)[i] = make_uint2(l0, l1);
}

// ===========================================================================
// Pre-pass: transpose + split: in [R][C] fp32 -> outHi/outLo [C][R] bf16
// ===========================================================================
__global__ void transpose_split(const float* __restrict__ in,
                                __nv_bfloat16* __restrict__ outH,
                                __nv_bfloat16* __restrict__ outL, int R, int C)
{
    __shared__ float t[32][33];
    int c0 = blockIdx.x * 32, r0 = blockIdx.y * 32;
    int tx = threadIdx.x, ty = threadIdx.y;   // 32 x 8
#pragma unroll
    for (int i = 0; i < 32; i += 8)
        t[ty + i][tx] = in[(size_t)(r0 + ty + i) * C + c0 + tx];
    __syncthreads();
#pragma unroll
    for (int i = 0; i < 32; i += 8) {
        float v = t[tx][ty + i];
        __nv_bfloat16 h = __float2bfloat16(v);
        float lof = v - __bfloat162float(h);
        size_t o = (size_t)(c0 + ty + i) * R + r0 + tx;
        outH[o] = h;
        outL[o] = __float2bfloat16(lof);
    }
}

// ===========================================================================
// 3xBF16 mma.sync GEMM (unchanged from R8, validated).
// ===========================================================================
#define SA 20
#define AW (128 * SA)
#define BW (256 * SA)
#define STAGE_WORDS (2*AW + 2*BW)
#define GEMM_DYN_SMEM (2 * STAGE_WORDS * 4)

__global__ __launch_bounds__(256, 1) void gemm_bf3(
    const __nv_bfloat16* __restrict__ Ah_, const __nv_bfloat16* __restrict__ Al_,
    const __nv_bfloat16* __restrict__ Bh_, const __nv_bfloat16* __restrict__ Bl_,
    const float* __restrict__ bias, float* __restrict__ C,
    int M, int N, int K)
{
    extern __shared__ uint32_t smw[];
    const int tid = threadIdx.x;
    const int wid = tid >> 5, lid = tid & 31;
    const int g = lid >> 2, t4 = lid & 3;
    const int warp_m = (wid & 1) * 64;
    const int warp_n = (wid >> 1) * 64;
    const int row0 = blockIdx.y * 128;
    const int col0 = blockIdx.x * 256;

    const uint32_t sb = smem_u32(smw);
    const int KW = K >> 1;
    const uint32_t* AwH = (const uint32_t*)Ah_ + (size_t)row0 * KW;
    const uint32_t* AwL = (const uint32_t*)Al_ + (size_t)row0 * KW;
    const uint32_t* BwH = (const uint32_t*)Bh_ + (size_t)col0 * KW;
    const uint32_t* BwL = (const uint32_t*)Bl_ + (size_t)col0 * KW;
    const int NC = K / 32;

    auto load_chunk = [&](int c, int s) {
        const int kw = c * 16;
        uint32_t st = sb + (uint32_t)(s * STAGE_WORDS) * 4;
#pragma unroll
        for (int i = 0; i < 2; i++) {
            int idx = i * 256 + tid;
            int r = idx >> 2, q = idx & 3;
            uint32_t off = (uint32_t)(r * SA + q * 4) * 4;
            cp_async16(st + off, AwH + (size_t)r * KW + kw + q * 4);
            cp_async16(st + AW * 4 + off, AwL + (size_t)r * KW + kw + q * 4);
        }
#pragma unroll
        for (int i = 0; i < 4; i++) {
            int idx = i * 256 + tid;
            int r = idx >> 2, q = idx & 3;
            uint32_t off = (uint32_t)(r * SA + q * 4) * 4;
            cp_async16(st + 2 * AW * 4 + off, BwH + (size_t)r * KW + kw + q * 4);
            cp_async16(st + (2 * AW + BW) * 4 + off, BwL + (size_t)r * KW + kw + q * 4);
        }
        cp_commit();
    };

    load_chunk(0, 0);
    load_chunk(1, 1);

    float acc[4][8][4];
#pragma unroll
    for (int mt = 0; mt < 4; mt++)
#pragma unroll
        for (int nt = 0; nt < 8; nt++)
#pragma unroll
            for (int r = 0; r < 4; r++) acc[mt][nt][r] = 0.f;

    int s = 0;
    for (int c = 0; c < NC; c++) {
        cp_wait<1>();
        __syncthreads();

        const uint32_t* AH = smw + s * STAGE_WORDS;
        const uint32_t* AL = AH + AW;
        const uint32_t* BH = AL + AW;
        const uint32_t* BL = BH + BW;

#pragma unroll
        for (int kk = 0; kk < 2; kk++) {
            const int kw = kk * 8;
            uint32_t ah[4][4], al[4][4];
#pragma unroll
            for (int mt = 0; mt < 4; mt++) {
                int base = (warp_m + mt * 16 + g) * SA + kw + t4;
                ah[mt][0] = AH[base];
                ah[mt][1] = AH[base + 8 * SA];
                ah[mt][2] = AH[base + 4];
                ah[mt][3] = AH[base + 8 * SA + 4];
                al[mt][0] = AL[base];
                al[mt][1] = AL[base + 8 * SA];
                al[mt][2] = AL[base + 4];
                al[mt][3] = AL[base + 8 * SA + 4];
            }
#pragma unroll
            for (int nt = 0; nt < 8; nt++) {
                int nb = (warp_n + nt * 8 + g) * SA + kw + t4;
                uint32_t bh[2], bl[2];
                bh[0] = BH[nb]; bh[1] = BH[nb + 4];
                bl[0] = BL[nb]; bl[1] = BL[nb + 4];
#pragma unroll
                for (int mt = 0; mt < 4; mt++) {
                    mma_bf16(acc[mt][nt], ah[mt], bh);
                    mma_bf16(acc[mt][nt], al[mt], bh);
                    mma_bf16(acc[mt][nt], ah[mt], bl);
                }
            }
        }

        __syncthreads();
        if (c + 2 < NC) load_chunk(c + 2, s);
        else            cp_commit();
        s ^= 1;
    }

#pragma unroll
    for (int mt = 0; mt < 4; mt++) {
        int r0 = row0 + warp_m + mt * 16 + g;
#pragma unroll
        for (int nt = 0; nt < 8; nt++) {
            int gc = col0 + warp_n + nt * 8 + 2 * t4;
            float b0 = bias[gc], b1 = bias[gc + 1];
            float2 v0 = make_float2(acc[mt][nt][0] + b0, acc[mt][nt][1] + b1);
            float2 v1 = make_float2(acc[mt][nt][2] + b0, acc[mt][nt][3] + b1);
            *(float2*)&C[(size_t)r0 * N + gc] = v0;
            *(float2*)&C[(size_t)(r0 + 8) * N + gc] = v1;
        }
    }
}

// ===========================================================================
// 3xBF16 causal flash attention. 2 CTAs/SM.
// smem layout (words, interleaved hi/lo: hi at 2w, lo at 2w+1; row stride 72):
//   Q  [128][72], K [64][72], Vt [64 d][72] (s-pairs), P per warp [16][72]
// ===========================================================================
#define TQ 128
#define TK 64
#define SIW 72
#define ATTN_SMEM ((128*SIW + 64*SIW + 64*SIW + 8*16*SIW) * 4)   // 110592 B

__global__ __launch_bounds__(256, 2) void attn_bf(
    const float* __restrict__ qkv, float* __restrict__ out)
{
    extern __shared__ uint32_t smw[];
    uint32_t* Qs = smw;                    // [128][SIW]
    uint32_t* Ks = Qs + 128 * SIW;         // [64][SIW]
    uint32_t* Vt = Ks + 64 * SIW;          // [64][SIW]  (rows = d, packed s-pairs)
    uint32_t* Ps = Vt + 64 * SIW;          // per warp [16][SIW]

    const int bh = blockIdx.x;
    const int b  = bh >> 4;
    const int h  = bh & 15;
    const int qt = (gridDim.y - 1) - blockIdx.y;   // heavy tiles first
    const int q0 = qt * TQ;

    const int tid = threadIdx.x;
    const int wid = tid >> 5, lid = tid & 31;
    const int g = lid >> 2, t4 = lid & 3;
    const int wm = wid * 16;
    uint32_t* Pw = Ps + wid * 16 * SIW;

    const float* base = qkv + (size_t)(b * SEQ) * QKV_N + h * HD;

    // ---- load + split Q tile [128][64] -> interleaved bf16 hi/lo ----
    for (int idx = tid; idx < TQ * 16; idx += 256) {
        int r = idx >> 4, q = idx & 15;
        float4 v = *(const float4*)&base[(size_t)(q0 + r) * QKV_N + q * 4];
        uint32_t h0, l0, h1, l1;
        bf16_split2(v.x, v.y, h0, l0);
        bf16_split2(v.z, v.w, h1, l1);
        *(uint4*)&Qs[r * SIW + 4 * q] = make_uint4(h0, l0, h1, l1);
    }

    float m_i[2] = {-1e30f, -1e30f};
    float l_i[2] = {0.f, 0.f};
    float oacc[8][4];
#pragma unroll
    for (int nt = 0; nt < 8; nt++)
#pragma unroll
        for (int r = 0; r < 4; r++) oacc[nt][r] = 0.f;

    const int nkt = 2 * qt + 2;
    for (int kt = 0; kt < nkt; kt++) {
        const int k0 = kt * TK;
        __syncthreads();
        // ---- load + split K (natural) and V (transposed [d][s]) ----
        for (int idx = tid; idx < TK * 16; idx += 256) {
            int r = idx >> 4, q = idx & 15;
            size_t gofs = (size_t)(k0 + r) * QKV_N + q * 4;
            float4 kv = *(const float4*)&base[DMODEL + gofs];
            uint32_t h0, l0, h1, l1;
            bf16_split2(kv.x, kv.y, h0, l0);
            bf16_split2(kv.z, kv.w, h1, l1);
            *(uint4*)&Ks[r * SIW + 4 * q] = make_uint4(h0, l0, h1, l1);

            float4 vv = *(const float4*)&base[2 * DMODEL + gofs];
            float va[4] = {vv.x, vv.y, vv.z, vv.w};
            __nv_bfloat16* vtb = (__nv_bfloat16*)Vt;
            int ubase = 4 * (r >> 1) + (r & 1);      // u16 index within row
#pragma unroll
            for (int j = 0; j < 4; j++) {
                int d = 4 * q + j;
                __nv_bfloat16 hb = __float2bfloat16(va[j]);
                float res = va[j] - __bfloat162float(hb);
                int u = d * SIW * 2 + ubase;
                vtb[u]     = hb;
                vtb[u + 2] = __float2bfloat16(res);
            }
        }
        __syncthreads();

        // Warp-level full skip
        if (k0 > q0 + wm + 15) continue;

        // ---- S = Q K^T ----
        float sacc[8][4];
#pragma unroll
        for (int nt = 0; nt < 8; nt++)
#pragma unroll
            for (int r = 0; r < 4; r++) sacc[nt][r] = 0.f;

#pragma unroll
        for (int sk = 0; sk < 4; sk++) {           // 4 k16 slices over d=64
            const int kwb = 16 * sk + 2 * t4;
            uint32_t ah[4], al[4];
            {
                uint2 p0 = *(uint2*)&Qs[(wm + g)     * SIW + kwb];
                uint2 p1 = *(uint2*)&Qs[(wm + g + 8) * SIW + kwb];
                uint2 p2 = *(uint2*)&Qs[(wm + g)     * SIW + kwb + 8];
                uint2 p3 = *(uint2*)&Qs[(wm + g + 8) * SIW + kwb + 8];
                ah[0] = p0.x; al[0] = p0.y;
                ah[1] = p1.x; al[1] = p1.y;
                ah[2] = p2.x; al[2] = p2.y;
                ah[3] = p3.x; al[3] = p3.y;
            }
#pragma unroll
            for (int nt = 0; nt < 8; nt++) {
                uint2 q0w = *(uint2*)&Ks[(nt * 8 + g) * SIW + kwb];
                uint2 q1w = *(uint2*)&Ks[(nt * 8 + g) * SIW + kwb + 8];
                uint32_t bhf[2] = {q0w.x, q1w.x};
                uint32_t blf[2] = {q0w.y, q1w.y};
                mma_bf16(sacc[nt], ah, bhf);
                mma_bf16(sacc[nt], al, bhf);
                mma_bf16(sacc[nt], ah, blf);
            }
        }

        // ---- causal mask ----
        if (k0 + TK - 1 > q0 + wm) {
            const int r0g = q0 + wm + g;
#pragma unroll
            for (int nt = 0; nt < 8; nt++) {
                int c0 = k0 + nt * 8 + 2 * t4;
                if (c0     > r0g)     sacc[nt][0] = -1e30f;
                if (c0 + 1 > r0g)     sacc[nt][1] = -1e30f;
                if (c0     > r0g + 8) sacc[nt][2] = -1e30f;
                if (c0 + 1 > r0g + 8) sacc[nt][3] = -1e30f;
            }
        }

        // ---- online softmax ----
        float rm[2];
        rm[0] = fmaxf(sacc[0][0], sacc[0][1]);
        rm[1] = fmaxf(sacc[0][2], sacc[0][3]);
#pragma unroll
        for (int nt = 1; nt < 8; nt++) {
            rm[0] = fmaxf(rm[0], fmaxf(sacc[nt][0], sacc[nt][1]));
            rm[1] = fmaxf(rm[1], fmaxf(sacc[nt][2], sacc[nt][3]));
        }
#pragma unroll
        for (int off = 1; off < 4; off <<= 1) {
            rm[0] = fmaxf(rm[0], __shfl_xor_sync(0xffffffffu, rm[0], off));
            rm[1] = fmaxf(rm[1], __shfl_xor_sync(0xffffffffu, rm[1], off));
        }
        float mn0 = fmaxf(m_i[0], rm[0]), mn1 = fmaxf(m_i[1], rm[1]);
        float sc0 = __expf(m_i[0] - mn0), sc1 = __expf(m_i[1] - mn1);
        float rs0 = 0.f, rs1 = 0.f;
#pragma unroll
        for (int nt = 0; nt < 8; nt++) {
            sacc[nt][0] = __expf(sacc[nt][0] - mn0); rs0 += sacc[nt][0];
            sacc[nt][1] = __expf(sacc[nt][1] - mn0); rs0 += sacc[nt][1];
            sacc[nt][2] = __expf(sacc[nt][2] - mn1); rs1 += sacc[nt][2];
            sacc[nt][3] = __expf(sacc[nt][3] - mn1); rs1 += sacc[nt][3];
        }
#pragma unroll
        for (int off = 1; off < 4; off <<= 1) {
            rs0 += __shfl_xor_sync(0xffffffffu, rs0, off);
            rs1 += __shfl_xor_sync(0xffffffffu, rs1, off);
        }
        l_i[0] = l_i[0] * sc0 + rs0;  m_i[0] = mn0;
        l_i[1] = l_i[1] * sc1 + rs1;  m_i[1] = mn1;
#pragma unroll
        for (int nt = 0; nt < 8; nt++) {
            oacc[nt][0] *= sc0; oacc[nt][1] *= sc0;
            oacc[nt][2] *= sc1; oacc[nt][3] *= sc1;
        }

        // ---- split P -> interleaved bf16 hi/lo in per-warp smem ----
#pragma unroll
        for (int nt = 0; nt < 8; nt++) {
            uint32_t hh, ll;
            bf16_split2(sacc[nt][0], sacc[nt][1], hh, ll);
            *(uint2*)&Pw[g * SIW + 2 * (nt * 4 + t4)] = make_uint2(hh, ll);
            bf16_split2(sacc[nt][2], sacc[nt][3], hh, ll);
            *(uint2*)&Pw[(g + 8) * SIW + 2 * (nt * 4 + t4)] = make_uint2(hh, ll);
        }
        __syncwarp();

        // ---- O += P @ V  (B = Vt [d][s-pairs]) ----
#pragma unroll
        for (int sk = 0; sk < 4; sk++) {           // 4 k16 slices over s=64
            const int kwb = 16 * sk + 2 * t4;
            uint32_t ah[4], al[4];
            {
                uint2 p0 = *(uint2*)&Pw[g       * SIW + kwb];
                uint2 p1 = *(uint2*)&Pw[(g + 8) * SIW + kwb];
                uint2 p2 = *(uint2*)&Pw[g       * SIW + kwb + 8];
                uint2 p3 = *(uint2*)&Pw[(g + 8) * SIW + kwb + 8];
                ah[0] = p0.x; al[0] = p0.y;
                ah[1] = p1.x; al[1] = p1.y;
                ah[2] = p2.x; al[2] = p2.y;
                ah[3] = p3.x; al[3] = p3.y;
            }
#pragma unroll
            for (int nt = 0; nt < 8; nt++) {
                uint2 v0w = *(uint2*)&Vt[(nt * 8 + g) * SIW + kwb];
                uint2 v1w = *(uint2*)&Vt[(nt * 8 + g) * SIW + kwb + 8];
                uint32_t bhf[2] = {v0w.x, v1w.x};
                uint32_t blf[2] = {v0w.y, v1w.y};
                mma_bf16(oacc[nt], ah, bhf);
                mma_bf16(oacc[nt], al, bhf);
                mma_bf16(oacc[nt], ah, blf);
            }
        }
        __syncwarp();
    }

    // ---- write output ----
    const float inv0 = 1.f / l_i[0], inv1 = 1.f / l_i[1];
    const size_t gr0 = (size_t)(b * SEQ + q0 + wm + g);
    float* ob = out + h * HD;
#pragma unroll
    for (int nt = 0; nt < 8; nt++) {
        int gc = nt * 8 + 2 * t4;
        *(float2*)&ob[gr0 * DMODEL + gc] =
            make_float2(oacc[nt][0] * inv0, oacc[nt][1] * inv0);
        *(float2*)&ob[(gr0 + 8) * DMODEL + gc] =
            make_float2(oacc[nt][2] * inv1, oacc[nt][3] * inv1);
    }
}

// ===========================================================================
extern "C" void kernel_launch(void* const* d_in, const int* in_sizes, int n_in,
                              void* d_out, int out_size)
{
    const float* hidden = (const float*)d_in[0];
    const float* w_attn = (const float*)d_in[1];
    const float* b_attn = (const float*)d_in[2];
    const float* w_proj = (const float*)d_in[3];
    const float* b_proj = (const float*)d_in[4];
    float* out = (float*)d_out;

    float* qkv = nullptr;
    float* att = nullptr;
    __nv_bfloat16 *wTh = nullptr, *wTl = nullptr, *xh = nullptr, *xl = nullptr;
    cudaGetSymbolAddress((void**)&qkv, g_qkv);
    cudaGetSymbolAddress((void**)&att, g_att);
    cudaGetSymbolAddress((void**)&wTh, g_wTh);
    cudaGetSymbolAddress((void**)&wTl, g_wTl);
    cudaGetSymbolAddress((void**)&xh,  g_xh);
    cudaGetSymbolAddress((void**)&xl,  g_xl);

    __nv_bfloat16* wTah = wTh;
    __nv_bfloat16* wTal = wTl;
    __nv_bfloat16* wTph = wTh + (size_t)QKV_N * DMODEL;
    __nv_bfloat16* wTpl = wTl + (size_t)QKV_N * DMODEL;

    cudaFuncSetAttribute(gemm_bf3, cudaFuncAttributeMaxDynamicSharedMemorySize,
                         GEMM_DYN_SMEM);
    cudaFuncSetAttribute(attn_bf, cudaFuncAttributeMaxDynamicSharedMemorySize,
                         ATTN_SMEM);

    // 0) Weights: transpose + split to packed bf16 hi/lo [N][K]
    {
        dim3 blk(32, 8);
        transpose_split<<<dim3(QKV_N / 32, DMODEL / 32), blk>>>(w_attn, wTah, wTal,
                                                                DMODEL, QKV_N);
        transpose_split<<<dim3(DMODEL / 32, DMODEL / 32), blk>>>(w_proj, wTph, wTpl,
                                                                 DMODEL, DMODEL);
    }

    // 1) hidden -> bf16 hi/lo
    {
        int n4 = (M_ROWS * DMODEL) / 4;
        split_pack<<<(n4 + 255) / 256, 256>>>(hidden, xh, xl, n4);
    }

    // 2) QKV projection (3xbf16 mma)
    {
        dim3 grid(QKV_N / 256, M_ROWS / 128);
        gemm_bf3<<<grid, 256, GEMM_DYN_SMEM>>>(xh, xl, wTah, wTal, b_attn, qkv,
                                               M_ROWS, QKV_N, DMODEL);
    }

    // 3) Causal attention (3xbf16 mma flash attention)
    {
        dim3 grid(BATCH * NHEAD, SEQ / TQ);
        attn_bf<<<grid, 256, ATTN_SMEM>>>(qkv, att);
    }

    // 4) att -> bf16 hi/lo
    {
        int n4 = (M_ROWS * DMODEL) / 4;
        split_pack<<<(n4 + 255) / 256, 256>>>(att, xh, xl, n4);
    }

    // 5) Output projection (3xbf16 mma)
    {
        dim3 grid(DMODEL / 256, M_ROWS / 128);
        gemm_bf3<<<grid, 256, GEMM_DYN_SMEM>>>(xh, xl, wTph, wTpl, b_proj, out,
                                               M_ROWS, DMODEL, DMODEL);
    }
}

// round 11
// speedup vs baseline: 1.1756x; 1.1756x over previous
#include <cuda_runtime.h>
#include <cuda_bf16.h>
#include <cstdint>
#include <math.h>

// Problem constants
#define BATCH 2
#define SEQ   2048
#define DMODEL 1024
#define NHEAD 16
#define HD    64
#define M_ROWS (BATCH*SEQ)        // 4096
#define QKV_N  (3*DMODEL)         // 3072

// Scratch (device globals; allocation is forbidden)
__device__ float g_qkv[(size_t)M_ROWS * QKV_N];    // 48 MB
__device__ float g_att[(size_t)M_ROWS * DMODEL];   // 16 MB
// bf16 hi/lo packed operands
__device__ __nv_bfloat16 g_wTh[(size_t)(QKV_N + DMODEL) * DMODEL];  // 8 MB
__device__ __nv_bfloat16 g_wTl[(size_t)(QKV_N + DMODEL) * DMODEL];  // 8 MB
__device__ __nv_bfloat16 g_xh[(size_t)M_ROWS * DMODEL];             // 8 MB
__device__ __nv_bfloat16 g_xl[(size_t)M_ROWS * DMODEL];             // 8 MB

// ===========================================================================
// PTX helpers
// ===========================================================================
__device__ __forceinline__ uint32_t smem_u32(const void* p) {
    uint32_t a;
    asm("{ .reg .u64 t; cvta.to.shared.u64 t, %1; cvt.u32.u64 %0, t; }"
        : "=r"(a) : "l"(p));
    return a;
}
__device__ __forceinline__ void cp_async16(uint32_t s, const void* g) {
    asm volatile("cp.async.cg.shared.global [%0], [%1], 16;" :: "r"(s), "l"(g));
}
__device__ __forceinline__ void cp_commit() {
    asm volatile("cp.async.commit_group;" ::: "memory");
}
template<int N> __device__ __forceinline__ void cp_wait() {
    asm volatile("cp.async.wait_group %0;" :: "n"(N) : "memory");
}

// bf16 mma: D[16x8] += A[16x16] * B[16x8]  (row.col)
__device__ __forceinline__ void mma_bf16(float* c, const uint32_t* a, const uint32_t* b) {
    asm volatile(
        "mma.sync.aligned.m16n8k16.row.col.f32.bf16.bf16.f32 "
        "{%0,%1,%2,%3}, {%4,%5,%6,%7}, {%8,%9}, {%0,%1,%2,%3};"
        : "+f"(c[0]), "+f"(c[1]), "+f"(c[2]), "+f"(c[3])
        : "r"(a[0]), "r"(a[1]), "r"(a[2]), "r"(a[3]), "r"(b[0]), "r"(b[1]));
}

// Split 2 fp32 -> packed bf16 hi word (x low half, y high) + lo residual word
__device__ __forceinline__ void bf16_split2(float x, float y, uint32_t& h, uint32_t& l) {
    asm("cvt.rn.bf16x2.f32 %0, %1, %2;" : "=r"(h) : "f"(y), "f"(x));
    float rx = x - __uint_as_float(h << 16);
    float ry = y - __uint_as_float(h & 0xFFFF0000u);
    asm("cvt.rn.bf16x2.f32 %0, %1, %2;" : "=r"(l) : "f"(ry), "f"(rx));
}

// ===========================================================================
// Pre-pass: elementwise split fp32 -> packed bf16 hi/lo
// ===========================================================================
__global__ void split_pack(const float* __restrict__ in,
                           __nv_bfloat16* __restrict__ hi,
                           __nv_bfloat16* __restrict__ lo, int n4)
{
    int i = blockIdx.x * blockDim.x + threadIdx.x;
    if (i >= n4) return;
    float4 v = *(const float4*)(in + (size_t)i * 4);
    uint32_t h0, h1, l0, l1;
    bf16_split2(v.x, v.y, h0, l0);
    bf16_split2(v.z, v.w, h1, l1);
    ((uint2*)hi)[i] = make_uint2(h0, h1);
    ((uint2*)lo)[i] = make_uint2(l0, l1);
}

// ===========================================================================
// Pre-pass: transpose + split: in [R][C] fp32 -> outHi/outLo [C][R] bf16
// ===========================================================================
__global__ void transpose_split(const float* __restrict__ in,
                                __nv_bfloat16* __restrict__ outH,
                                __nv_bfloat16* __restrict__ outL, int R, int C)
{
    __shared__ float t[32][33];
    int c0 = blockIdx.x * 32, r0 = blockIdx.y * 32;
    int tx = threadIdx.x, ty = threadIdx.y;   // 32 x 8
#pragma unroll
    for (int i = 0; i < 32; i += 8)
        t[ty + i][tx] = in[(size_t)(r0 + ty + i) * C + c0 + tx];
    __syncthreads();
#pragma unroll
    for (int i = 0; i < 32; i += 8) {
        float v = t[tx][ty + i];
        __nv_bfloat16 h = __float2bfloat16(v);
        float lof = v - __bfloat162float(h);
        size_t o = (size_t)(c0 + ty + i) * R + r0 + tx;
        outH[o] = h;
        outL[o] = __float2bfloat16(lof);
    }
}

// ===========================================================================
// 3xBF16 mma.sync GEMM (unchanged, validated in R8).
// ===========================================================================
#define SA 20
#define AW (128 * SA)
#define BW (256 * SA)
#define STAGE_WORDS (2*AW + 2*BW)
#define GEMM_DYN_SMEM (2 * STAGE_WORDS * 4)

__global__ __launch_bounds__(256, 1) void gemm_bf3(
    const __nv_bfloat16* __restrict__ Ah_, const __nv_bfloat16* __restrict__ Al_,
    const __nv_bfloat16* __restrict__ Bh_, const __nv_bfloat16* __restrict__ Bl_,
    const float* __restrict__ bias, float* __restrict__ C,
    int M, int N, int K)
{
    extern __shared__ uint32_t smw[];
    const int tid = threadIdx.x;
    const int wid = tid >> 5, lid = tid & 31;
    const int g = lid >> 2, t4 = lid & 3;
    const int warp_m = (wid & 1) * 64;
    const int warp_n = (wid >> 1) * 64;
    const int row0 = blockIdx.y * 128;
    const int col0 = blockIdx.x * 256;

    const uint32_t sb = smem_u32(smw);
    const int KW = K >> 1;
    const uint32_t* AwH = (const uint32_t*)Ah_ + (size_t)row0 * KW;
    const uint32_t* AwL = (const uint32_t*)Al_ + (size_t)row0 * KW;
    const uint32_t* BwH = (const uint32_t*)Bh_ + (size_t)col0 * KW;
    const uint32_t* BwL = (const uint32_t*)Bl_ + (size_t)col0 * KW;
    const int NC = K / 32;

    auto load_chunk = [&](int c, int s) {
        const int kw = c * 16;
        uint32_t st = sb + (uint32_t)(s * STAGE_WORDS) * 4;
#pragma unroll
        for (int i = 0; i < 2; i++) {
            int idx = i * 256 + tid;
            int r = idx >> 2, q = idx & 3;
            uint32_t off = (uint32_t)(r * SA + q * 4) * 4;
            cp_async16(st + off, AwH + (size_t)r * KW + kw + q * 4);
            cp_async16(st + AW * 4 + off, AwL + (size_t)r * KW + kw + q * 4);
        }
#pragma unroll
        for (int i = 0; i < 4; i++) {
            int idx = i * 256 + tid;
            int r = idx >> 2, q = idx & 3;
            uint32_t off = (uint32_t)(r * SA + q * 4) * 4;
            cp_async16(st + 2 * AW * 4 + off, BwH + (size_t)r * KW + kw + q * 4);
            cp_async16(st + (2 * AW + BW) * 4 + off, BwL + (size_t)r * KW + kw + q * 4);
        }
        cp_commit();
    };

    load_chunk(0, 0);
    load_chunk(1, 1);

    float acc[4][8][4];
#pragma unroll
    for (int mt = 0; mt < 4; mt++)
#pragma unroll
        for (int nt = 0; nt < 8; nt++)
#pragma unroll
            for (int r = 0; r < 4; r++) acc[mt][nt][r] = 0.f;

    int s = 0;
    for (int c = 0; c < NC; c++) {
        cp_wait<1>();
        __syncthreads();

        const uint32_t* AH = smw + s * STAGE_WORDS;
        const uint32_t* AL = AH + AW;
        const uint32_t* BH = AL + AW;
        const uint32_t* BL = BH + BW;

#pragma unroll
        for (int kk = 0; kk < 2; kk++) {
            const int kw = kk * 8;
            uint32_t ah[4][4], al[4][4];
#pragma unroll
            for (int mt = 0; mt < 4; mt++) {
                int base = (warp_m + mt * 16 + g) * SA + kw + t4;
                ah[mt][0] = AH[base];
                ah[mt][1] = AH[base + 8 * SA];
                ah[mt][2] = AH[base + 4];
                ah[mt][3] = AH[base + 8 * SA + 4];
                al[mt][0] = AL[base];
                al[mt][1] = AL[base + 8 * SA];
                al[mt][2] = AL[base + 4];
                al[mt][3] = AL[base + 8 * SA + 4];
            }
#pragma unroll
            for (int nt = 0; nt < 8; nt++) {
                int nb = (warp_n + nt * 8 + g) * SA + kw + t4;
                uint32_t bh[2], bl[2];
                bh[0] = BH[nb]; bh[1] = BH[nb + 4];
                bl[0] = BL[nb]; bl[1] = BL[nb + 4];
#pragma unroll
                for (int mt = 0; mt < 4; mt++) {
                    mma_bf16(acc[mt][nt], ah[mt], bh);
                    mma_bf16(acc[mt][nt], al[mt], bh);
                    mma_bf16(acc[mt][nt], ah[mt], bl);
                }
            }
        }

        __syncthreads();
        if (c + 2 < NC) load_chunk(c + 2, s);
        else            cp_commit();
        s ^= 1;
    }

#pragma unroll
    for (int mt = 0; mt < 4; mt++) {
        int r0 = row0 + warp_m + mt * 16 + g;
#pragma unroll
        for (int nt = 0; nt < 8; nt++) {
            int gc = col0 + warp_n + nt * 8 + 2 * t4;
            float b0 = bias[gc], b1 = bias[gc + 1];
            float2 v0 = make_float2(acc[mt][nt][0] + b0, acc[mt][nt][1] + b1);
            float2 v1 = make_float2(acc[mt][nt][2] + b0, acc[mt][nt][3] + b1);
            *(float2*)&C[(size_t)r0 * N + gc] = v0;
            *(float2*)&C[(size_t)(r0 + 8) * N + gc] = v1;
        }
    }
}

// ===========================================================================
// 3xBF16 causal flash attention, 2 CTAs/SM.
// Q  [128 r][SIW=72 w]  interleaved hi/lo (hi at 2w, lo at 2w+1)
// K  [64 s][72 w]       interleaved hi/lo
// Vp [32 s-pair][VPW=136 w]: word 2d = bf16x2(v[2sp][d], v[2sp+1][d]) hi,
//                            word 2d+1 = lo residual  (pair-packed for B-frag)
// P  per warp [16 r][72 w] interleaved hi/lo pairs
// ===========================================================================
#define TQ 128
#define TK 64
#define SIW 72
#define VPW 136
#define ATTN_SMEM ((128*SIW + 64*SIW + 32*VPW + 8*16*SIW) * 4)   // 109568 B

__global__ __launch_bounds__(256, 2) void attn_bf(
    const float* __restrict__ qkv, float* __restrict__ out)
{
    extern __shared__ uint32_t smw[];
    uint32_t* Qs = smw;                    // [128][SIW]
    uint32_t* Ks = Qs + 128 * SIW;         // [64][SIW]
    uint32_t* Vp = Ks + 64 * SIW;          // [32][VPW]
    uint32_t* Ps = Vp + 32 * VPW;          // per warp [16][SIW]

    const int bh = blockIdx.x;
    const int b  = bh >> 4;
    const int h  = bh & 15;
    const int qt = (gridDim.y - 1) - blockIdx.y;   // heavy tiles first
    const int q0 = qt * TQ;

    const int tid = threadIdx.x;
    const int wid = tid >> 5, lid = tid & 31;
    const int g = lid >> 2, t4 = lid & 3;
    const int wm = wid * 16;
    uint32_t* Pw = Ps + wid * 16 * SIW;

    const float* base = qkv + (size_t)(b * SEQ) * QKV_N + h * HD;

    // ---- load + split Q tile [128][64] -> interleaved bf16 hi/lo ----
    for (int idx = tid; idx < TQ * 16; idx += 256) {
        int r = idx >> 4, q = idx & 15;
        float4 v = *(const float4*)&base[(size_t)(q0 + r) * QKV_N + q * 4];
        uint32_t h0, l0, h1, l1;
        bf16_split2(v.x, v.y, h0, l0);
        bf16_split2(v.z, v.w, h1, l1);
        *(uint4*)&Qs[r * SIW + 4 * q] = make_uint4(h0, l0, h1, l1);
    }

    float m_i[2] = {-1e30f, -1e30f};
    float l_i[2] = {0.f, 0.f};
    float oacc[8][4];
#pragma unroll
    for (int nt = 0; nt < 8; nt++)
#pragma unroll
        for (int r = 0; r < 4; r++) oacc[nt][r] = 0.f;

    const int nkt = 2 * qt + 2;
    for (int kt = 0; kt < nkt; kt++) {
        const int k0 = kt * TK;
        __syncthreads();

        // ---- K: natural [s][d], interleaved hi/lo ----
        for (int idx = tid; idx < TK * 16; idx += 256) {
            int r = idx >> 4, q = idx & 15;
            float4 kv = *(const float4*)&base[DMODEL + (size_t)(k0 + r) * QKV_N + q * 4];
            uint32_t h0, l0, h1, l1;
            bf16_split2(kv.x, kv.y, h0, l0);
            bf16_split2(kv.z, kv.w, h1, l1);
            *(uint4*)&Ks[r * SIW + 4 * q] = make_uint4(h0, l0, h1, l1);
        }
        // ---- V: pair-packed [sp][2d] -- two rows loaded, packed, 2x STS.128 ----
        for (int idx = tid; idx < (TK / 2) * 16; idx += 256) {
            int sp = idx >> 4, q = idx & 15;
            const float* v0p = &base[2 * DMODEL + (size_t)(k0 + 2 * sp) * QKV_N + q * 4];
            float4 va = *(const float4*)v0p;
            float4 vb = *(const float4*)(v0p + QKV_N);
            uint32_t h0, l0, h1, l1, h2, l2, h3, l3;
            bf16_split2(va.x, vb.x, h0, l0);
            bf16_split2(va.y, vb.y, h1, l1);
            bf16_split2(va.z, vb.z, h2, l2);
            bf16_split2(va.w, vb.w, h3, l3);
            *(uint4*)&Vp[sp * VPW + 8 * q]     = make_uint4(h0, l0, h1, l1);
            *(uint4*)&Vp[sp * VPW + 8 * q + 4] = make_uint4(h2, l2, h3, l3);
        }
        __syncthreads();

        // Warp-level full skip
        if (k0 > q0 + wm + 15) continue;

        // ---- S = Q K^T ----
        float sacc[8][4];
#pragma unroll
        for (int nt = 0; nt < 8; nt++)
#pragma unroll
            for (int r = 0; r < 4; r++) sacc[nt][r] = 0.f;

#pragma unroll
        for (int sk = 0; sk < 4; sk++) {           // 4 k16 slices over d=64
            const int kwb = 16 * sk + 2 * t4;
            uint32_t ah[4], al[4];
            {
                uint2 p0 = *(uint2*)&Qs[(wm + g)     * SIW + kwb];
                uint2 p1 = *(uint2*)&Qs[(wm + g + 8) * SIW + kwb];
                uint2 p2 = *(uint2*)&Qs[(wm + g)     * SIW + kwb + 8];
                uint2 p3 = *(uint2*)&Qs[(wm + g + 8) * SIW + kwb + 8];
                ah[0] = p0.x; al[0] = p0.y;
                ah[1] = p1.x; al[1] = p1.y;
                ah[2] = p2.x; al[2] = p2.y;
                ah[3] = p3.x; al[3] = p3.y;
            }
#pragma unroll
            for (int nt = 0; nt < 8; nt++) {
                uint2 q0w = *(uint2*)&Ks[(nt * 8 + g) * SIW + kwb];
                uint2 q1w = *(uint2*)&Ks[(nt * 8 + g) * SIW + kwb + 8];
                uint32_t bhf[2] = {q0w.x, q1w.x};
                uint32_t blf[2] = {q0w.y, q1w.y};
                mma_bf16(sacc[nt], ah, bhf);
                mma_bf16(sacc[nt], al, bhf);
                mma_bf16(sacc[nt], ah, blf);
            }
        }

        // ---- causal mask ----
        if (k0 + TK - 1 > q0 + wm) {
            const int r0g = q0 + wm + g;
#pragma unroll
            for (int nt = 0; nt < 8; nt++) {
                int c0 = k0 + nt * 8 + 2 * t4;
                if (c0     > r0g)     sacc[nt][0] = -1e30f;
                if (c0 + 1 > r0g)     sacc[nt][1] = -1e30f;
                if (c0     > r0g + 8) sacc[nt][2] = -1e30f;
                if (c0 + 1 > r0g + 8) sacc[nt][3] = -1e30f;
            }
        }

        // ---- online softmax ----
        float rm[2];
        rm[0] = fmaxf(sacc[0][0], sacc[0][1]);
        rm[1] = fmaxf(sacc[0][2], sacc[0][3]);
#pragma unroll
        for (int nt = 1; nt < 8; nt++) {
            rm[0] = fmaxf(rm[0], fmaxf(sacc[nt][0], sacc[nt][1]));
            rm[1] = fmaxf(rm[1], fmaxf(sacc[nt][2], sacc[nt][3]));
        }
#pragma unroll
        for (int off = 1; off < 4; off <<= 1) {
            rm[0] = fmaxf(rm[0], __shfl_xor_sync(0xffffffffu, rm[0], off));
            rm[1] = fmaxf(rm[1], __shfl_xor_sync(0xffffffffu, rm[1], off));
        }
        float mn0 = fmaxf(m_i[0], rm[0]), mn1 = fmaxf(m_i[1], rm[1]);
        float sc0 = __expf(m_i[0] - mn0), sc1 = __expf(m_i[1] - mn1);
        float rs0 = 0.f, rs1 = 0.f;
#pragma unroll
        for (int nt = 0; nt < 8; nt++) {
            sacc[nt][0] = __expf(sacc[nt][0] - mn0); rs0 += sacc[nt][0];
            sacc[nt][1] = __expf(sacc[nt][1] - mn0); rs0 += sacc[nt][1];
            sacc[nt][2] = __expf(sacc[nt][2] - mn1); rs1 += sacc[nt][2];
            sacc[nt][3] = __expf(sacc[nt][3] - mn1); rs1 += sacc[nt][3];
        }
#pragma unroll
        for (int off = 1; off < 4; off <<= 1) {
            rs0 += __shfl_xor_sync(0xffffffffu, rs0, off);
            rs1 += __shfl_xor_sync(0xffffffffu, rs1, off);
        }
        l_i[0] = l_i[0] * sc0 + rs0;  m_i[0] = mn0;
        l_i[1] = l_i[1] * sc1 + rs1;  m_i[1] = mn1;
#pragma unroll
        for (int nt = 0; nt < 8; nt++) {
            oacc[nt][0] *= sc0; oacc[nt][1] *= sc0;
            oacc[nt][2] *= sc1; oacc[nt][3] *= sc1;
        }

        // ---- split P -> interleaved bf16 hi/lo in per-warp smem ----
#pragma unroll
        for (int nt = 0; nt < 8; nt++) {
            uint32_t hh, ll;
            bf16_split2(sacc[nt][0], sacc[nt][1], hh, ll);
            *(uint2*)&Pw[g * SIW + 2 * (nt * 4 + t4)] = make_uint2(hh, ll);
            bf16_split2(sacc[nt][2], sacc[nt][3], hh, ll);
            *(uint2*)&Pw[(g + 8) * SIW + 2 * (nt * 4 + t4)] = make_uint2(hh, ll);
        }
        __syncwarp();

        // ---- O += P @ V  (B = Vp pair-packed) ----
#pragma unroll
        for (int sk = 0; sk < 4; sk++) {           // 4 k16 slices over s=64
            const int kwb = 16 * sk + 2 * t4;
            uint32_t ah[4], al[4];
            {
                uint2 p0 = *(uint2*)&Pw[g       * SIW + kwb];
                uint2 p1 = *(uint2*)&Pw[(g + 8) * SIW + kwb];
                uint2 p2 = *(uint2*)&Pw[g       * SIW + kwb + 8];
                uint2 p3 = *(uint2*)&Pw[(g + 8) * SIW + kwb + 8];
                ah[0] = p0.x; al[0] = p0.y;
                ah[1] = p1.x; al[1] = p1.y;
                ah[2] = p2.x; al[2] = p2.y;
                ah[3] = p3.x; al[3] = p3.y;
            }
#pragma unroll
            for (int nt = 0; nt < 8; nt++) {
                int cw = 2 * (nt * 8 + g);
                uint2 v0w = *(uint2*)&Vp[(sk * 8 + t4)     * VPW + cw];
                uint2 v1w = *(uint2*)&Vp[(sk * 8 + t4 + 4) * VPW + cw];
                uint32_t bhf[2] = {v0w.x, v1w.x};
                uint32_t blf[2] = {v0w.y, v1w.y};
                mma_bf16(oacc[nt], ah, bhf);
                mma_bf16(oacc[nt], al, bhf);
                mma_bf16(oacc[nt], ah, blf);
            }
        }
        __syncwarp();
    }

    // ---- write output ----
    const float inv0 = 1.f / l_i[0], inv1 = 1.f / l_i[1];
    const size_t gr0 = (size_t)(b * SEQ + q0 + wm + g);
    float* ob = out + h * HD;
#pragma unroll
    for (int nt = 0; nt < 8; nt++) {
        int gc = nt * 8 + 2 * t4;
        *(float2*)&ob[gr0 * DMODEL + gc] =
            make_float2(oacc[nt][0] * inv0, oacc[nt][1] * inv0);
        *(float2*)&ob[(gr0 + 8) * DMODEL + gc] =
            make_float2(oacc[nt][2] * inv1, oacc[nt][3] * inv1);
    }
}

// ===========================================================================
extern "C" void kernel_launch(void* const* d_in, const int* in_sizes, int n_in,
                              void* d_out, int out_size)
{
    const float* hidden = (const float*)d_in[0];
    const float* w_attn = (const float*)d_in[1];
    const float* b_attn = (const float*)d_in[2];
    const float* w_proj = (const float*)d_in[3];
    const float* b_proj = (const float*)d_in[4];
    float* out = (float*)d_out;

    float* qkv = nullptr;
    float* att = nullptr;
    __nv_bfloat16 *wTh = nullptr, *wTl = nullptr, *xh = nullptr, *xl = nullptr;
    cudaGetSymbolAddress((void**)&qkv, g_qkv);
    cudaGetSymbolAddress((void**)&att, g_att);
    cudaGetSymbolAddress((void**)&wTh, g_wTh);
    cudaGetSymbolAddress((void**)&wTl, g_wTl);
    cudaGetSymbolAddress((void**)&xh,  g_xh);
    cudaGetSymbolAddress((void**)&xl,  g_xl);

    __nv_bfloat16* wTah = wTh;
    __nv_bfloat16* wTal = wTl;
    __nv_bfloat16* wTph = wTh + (size_t)QKV_N * DMODEL;
    __nv_bfloat16* wTpl = wTl + (size_t)QKV_N * DMODEL;

    cudaFuncSetAttribute(gemm_bf3, cudaFuncAttributeMaxDynamicSharedMemorySize,
                         GEMM_DYN_SMEM);
    cudaFuncSetAttribute(attn_bf, cudaFuncAttributeMaxDynamicSharedMemorySize,
                         ATTN_SMEM);

    // 0) Weights: transpose + split to packed bf16 hi/lo [N][K]
    {
        dim3 blk(32, 8);
        transpose_split<<<dim3(QKV_N / 32, DMODEL / 32), blk>>>(w_attn, wTah, wTal,
                                                                DMODEL, QKV_N);
        transpose_split<<<dim3(DMODEL / 32, DMODEL / 32), blk>>>(w_proj, wTph, wTpl,
                                                                 DMODEL, DMODEL);
    }

    // 1) hidden -> bf16 hi/lo
    {
        int n4 = (M_ROWS * DMODEL) / 4;
        split_pack<<<(n4 + 255) / 256, 256>>>(hidden, xh, xl, n4);
    }

    // 2) QKV projection (3xbf16 mma)
    {
        dim3 grid(QKV_N / 256, M_ROWS / 128);
        gemm_bf3<<<grid, 256, GEMM_DYN_SMEM>>>(xh, xl, wTah, wTal, b_attn, qkv,
                                               M_ROWS, QKV_N, DMODEL);
    }

    // 3) Causal attention (3xbf16 mma flash attention, pair-packed V)
    {
        dim3 grid(BATCH * NHEAD, SEQ / TQ);
        attn_bf<<<grid, 256, ATTN_SMEM>>>(qkv, att);
    }

    // 4) att -> bf16 hi/lo
    {
        int n4 = (M_ROWS * DMODEL) / 4;
        split_pack<<<(n4 + 255) / 256, 256>>>(att, xh, xl, n4);
    }

    // 5) Output projection (3xbf16 mma)
    {
        dim3 grid(DMODEL / 256, M_ROWS / 128);
        gemm_bf3<<<grid, 256, GEMM_DYN_SMEM>>>(xh, xl, wTph, wTpl, b_proj, out,
                                               M_ROWS, DMODEL, DMODEL);
    }
}